// round 1
// baseline (speedup 1.0000x reference)
#include <cuda_runtime.h>

#define NV 4096
#define CV 64
#define ALPHA 0.2f

// ---------------- device scratch (no allocations allowed) ----------------
__device__ float g_Wh[NV * CV];     // H @ W
__device__ float g_e1[NV];
__device__ float g_e2[NV];
__device__ float g_E1[NV];          // exp(e2)
__device__ float g_E2[NV];          // exp(alpha*e2)
__device__ float g_A[NV];           // exp(e1 - m)
__device__ float g_B[NV];           // exp(alpha*e1 - m)
__device__ float g_thE[NV];         // exp(-e1): branch threshold in E1 space
__device__ float g_dinv[NV];        // 1/denominator
__device__ float g_part[4][NV * CV];// j-split partial sums

// ---------------- K1: Wh = H@W, plus e1 = Wh@a1, e2 = Wh@a2 ----------------
__global__ __launch_bounds__(256) void k1_wh(const float* __restrict__ H,
                                             const float* __restrict__ W,
                                             const float* __restrict__ a) {
    __shared__ float Hs[64][68];   // pad 68: conflict-free scalar reads
    __shared__ float Ws[64][64];
    int tid = threadIdx.x;
    int il = tid >> 2;     // local row 0..63
    int cg = tid & 3;      // column group of 16
    int row0 = blockIdx.x * 64;

    float acc[16];
#pragma unroll
    for (int c = 0; c < 16; c++) acc[c] = 0.f;

    for (int kk = 0; kk < 256; kk += 64) {
#pragma unroll
        for (int t = 0; t < 4; t++) {
            int u = tid + t * 256;          // 0..1023
            int r = u >> 4, c4 = u & 15;
            float4 hv = *(const float4*)&H[(size_t)(row0 + r) * 256 + kk + c4 * 4];
            *(float4*)&Hs[r][c4 * 4] = hv;
            float4 wv = *(const float4*)&W[(size_t)(kk + r) * 64 + c4 * 4];
            *(float4*)&Ws[r][c4 * 4] = wv;
        }
        __syncthreads();
#pragma unroll 8
        for (int k = 0; k < 64; k++) {
            float h = Hs[il][k];
            const float4* wr = (const float4*)&Ws[k][cg * 16];
#pragma unroll
            for (int q = 0; q < 4; q++) {
                float4 w4 = wr[q];
                acc[q * 4 + 0] += h * w4.x;
                acc[q * 4 + 1] += h * w4.y;
                acc[q * 4 + 2] += h * w4.z;
                acc[q * 4 + 3] += h * w4.w;
            }
        }
        __syncthreads();
    }

    int i = row0 + il;
#pragma unroll
    for (int q = 0; q < 4; q++) {
        float4 v = make_float4(acc[q * 4 + 0], acc[q * 4 + 1], acc[q * 4 + 2], acc[q * 4 + 3]);
        *(float4*)&g_Wh[(size_t)i * 64 + cg * 16 + q * 4] = v;
    }
    // e1/e2 partial dot with a1/a2 over this thread's 16 columns
    float p1 = 0.f, p2 = 0.f;
#pragma unroll
    for (int c = 0; c < 16; c++) {
        p1 += acc[c] * __ldg(&a[cg * 16 + c]);
        p2 += acc[c] * __ldg(&a[64 + cg * 16 + c]);
    }
    p1 += __shfl_xor_sync(0xffffffffu, p1, 1);
    p1 += __shfl_xor_sync(0xffffffffu, p1, 2);
    p2 += __shfl_xor_sync(0xffffffffu, p2, 1);
    p2 += __shfl_xor_sync(0xffffffffu, p2, 2);
    if (cg == 0) { g_e1[i] = p1; g_e2[i] = p2; }
}

// ---------------- K1b: E1 = exp(e2), E2 = exp(alpha*e2) ----------------
__global__ __launch_bounds__(256) void k1b_exp() {
    int j = blockIdx.x * 256 + threadIdx.x;
    float v = g_e2[j];
    g_E1[j] = __expf(v);
    g_E2[j] = __expf(ALPHA * v);
}

// ---------------- K2: per-row m, A, B, thE, 1/denominator ----------------
// 256 blocks * 16 rows. Per row, 16 threads each sum a contiguous 256-j range.
__global__ __launch_bounds__(256) void k2_denom() {
    __shared__ float red[8];
    int tid = threadIdx.x;

    // block-local reduction of max(e2) (identical in every block -> deterministic)
    float mx = -1e30f;
#pragma unroll
    for (int t = 0; t < 4; t++) {
        float4 v = ((const float4*)g_e2)[tid + t * 256];
        mx = fmaxf(fmaxf(mx, v.x), fmaxf(fmaxf(v.y, v.z), v.w));
    }
#pragma unroll
    for (int o = 16; o > 0; o >>= 1) mx = fmaxf(mx, __shfl_xor_sync(0xffffffffu, mx, o));
    if ((tid & 31) == 0) red[tid >> 5] = mx;
    __syncthreads();
    float e2max;
    {
        float v = red[0];
#pragma unroll
        for (int w = 1; w < 8; w++) v = fmaxf(v, red[w]);
        e2max = v;
    }

    int il = tid >> 4;      // 0..15 rows
    int sub = tid & 15;     // 16 threads per row
    int i = blockIdx.x * 16 + il;
    float e1v = g_e1[i];
    float s = e1v + e2max;
    float m = s > 0.f ? s : ALPHA * s;
    float A = __expf(e1v - m);
    float B = __expf(ALPHA * e1v - m);
    float thE = __expf(-e1v);   // E1_j > thE  <=>  e1+e2_j > 0

    float d = 0.f;
    int j0 = sub * 256;
#pragma unroll 4
    for (int t = 0; t < 64; t++) {
        float4 E1v = *(const float4*)&g_E1[j0 + t * 4];
        float4 E2v = *(const float4*)&g_E2[j0 + t * 4];
        d += (E1v.x > thE) ? A * E1v.x : B * E2v.x;
        d += (E1v.y > thE) ? A * E1v.y : B * E2v.y;
        d += (E1v.z > thE) ? A * E1v.z : B * E2v.z;
        d += (E1v.w > thE) ? A * E1v.w : B * E2v.w;
    }
#pragma unroll
    for (int o = 8; o > 0; o >>= 1) d += __shfl_xor_sync(0xffffffffu, d, o);
    if (sub == 0) {
        g_A[i] = A; g_B[i] = B; g_thE[i] = thE;
        g_dinv[i] = 1.f / d;
    }
}

// ---------------- K3: masked weighted sum (the big one) ----------------
// Block = 64 rows x 64 cols, j split into 4 segments of 1024 -> 256 blocks.
// Per 64-j chunk: build w[64][64] tile from adj + factored exps, then
// accumulate acc += w * Wh_chunk with packed fp32x2 FMA.
__global__ __launch_bounds__(256) void k3_main(const int* __restrict__ adj) {
    __shared__ float Whs[64 * 64];       // 16 KB
    __shared__ float ws[64][68];         // padded: conflict-free
    __shared__ float E1s[1024], E2ss[1024];

    int tid = threadIdx.x;
    int il = tid >> 2;     // row 0..63
    int cg = tid & 3;      // 16-col group
    int br = blockIdx.x >> 2;
    int jseg = blockIdx.x & 3;
    int i = br * 64 + il;
    int jbase = jseg * 1024;

#pragma unroll
    for (int t = 0; t < 4; t++) {
        int u = tid + t * 256;
        E1s[u] = g_E1[jbase + u];
        E2ss[u] = g_E2[jbase + u];
    }
    float A = g_A[i], B = g_B[i], thE = g_thE[i];

    unsigned long long acc[8];
#pragma unroll
    for (int q = 0; q < 8; q++) acc[q] = 0ull;

    const int* adjRow = adj + (size_t)i * NV + jbase;

    for (int ch = 0; ch < 1024; ch += 64) {
        __syncthreads();   // protect smem reuse (also covers E1s preload on iter 0)
        // load Wh chunk
#pragma unroll
        for (int t = 0; t < 4; t++) {
            int u = tid + t * 256;
            int r = u >> 4, c4 = u & 15;
            *(float4*)&Whs[r * 64 + c4 * 4] =
                *(const float4*)&g_Wh[(size_t)(jbase + ch + r) * 64 + c4 * 4];
        }
        // build masked-weight tile: this thread covers (row il, j = ch+cg*16 .. +15)
        int jw = ch + cg * 16;
#pragma unroll
        for (int q = 0; q < 4; q++) {
            int4 av = *(const int4*)&adjRow[jw + q * 4];
            float E1a = E1s[jw + q * 4 + 0], E2a = E2ss[jw + q * 4 + 0];
            float E1b = E1s[jw + q * 4 + 1], E2b = E2ss[jw + q * 4 + 1];
            float E1c = E1s[jw + q * 4 + 2], E2c = E2ss[jw + q * 4 + 2];
            float E1d = E1s[jw + q * 4 + 3], E2d = E2ss[jw + q * 4 + 3];
            float w0 = (av.x > 0) ? ((E1a > thE) ? A * E1a : B * E2a) : 0.f;
            float w1 = (av.y > 0) ? ((E1b > thE) ? A * E1b : B * E2b) : 0.f;
            float w2 = (av.z > 0) ? ((E1c > thE) ? A * E1c : B * E2c) : 0.f;
            float w3 = (av.w > 0) ? ((E1d > thE) ? A * E1d : B * E2d) : 0.f;
            *(float4*)&ws[il][cg * 16 + q * 4] = make_float4(w0, w1, w2, w3);
        }
        __syncthreads();
        // accumulate: acc[c0..c15] += w[il][jj] * Wh[jj][c]
        const ulonglong2* wh2 = (const ulonglong2*)Whs;
#pragma unroll 8
        for (int jj = 0; jj < 64; jj++) {
            float wv = ws[il][jj];
            unsigned long long wp;
            asm("mov.b64 %0, {%1, %1};" : "=l"(wp) : "f"(wv));
            const ulonglong2* row = &wh2[jj * 16 + cg * 4];
#pragma unroll
            for (int q = 0; q < 4; q++) {
                ulonglong2 b = row[q];
                asm("fma.rn.f32x2 %0, %1, %2, %0;" : "+l"(acc[q * 2 + 0]) : "l"(wp), "l"(b.x));
                asm("fma.rn.f32x2 %0, %1, %2, %0;" : "+l"(acc[q * 2 + 1]) : "l"(wp), "l"(b.y));
            }
        }
    }
    // packed f32x2 bit-layout == two consecutive floats: store raw
    unsigned long long* dst = (unsigned long long*)&g_part[jseg][(size_t)i * 64 + cg * 16];
#pragma unroll
    for (int q = 0; q < 8; q++) dst[q] = acc[q];
}

// ---------------- K4: combine partials, scale by 1/denom, ELU ----------------
__global__ __launch_bounds__(256) void k4_out(float* __restrict__ out) {
    int idx = blockIdx.x * 256 + threadIdx.x;   // 0 .. N*C-1
    float v = g_part[0][idx] + g_part[1][idx] + g_part[2][idx] + g_part[3][idx];
    int i = idx >> 6;
    v *= g_dinv[i];
    out[idx] = v > 0.f ? v : (__expf(v) - 1.f);
}

// ---------------- launch ----------------
extern "C" void kernel_launch(void* const* d_in, const int* in_sizes, int n_in,
                              void* d_out, int out_size) {
    const float* H   = (const float*)d_in[0];
    const int*   adj = (const int*)d_in[1];
    const float* W   = (const float*)d_in[2];
    const float* a   = (const float*)d_in[3];
    float* out = (float*)d_out;

    k1_wh<<<64, 256>>>(H, W, a);
    k1b_exp<<<16, 256>>>();
    k2_denom<<<256, 256>>>();
    k3_main<<<256, 256>>>(adj);
    k4_out<<<1024, 256>>>(out);
}

// round 3
// speedup vs baseline: 3.6148x; 3.6148x over previous
#include <cuda_runtime.h>
#include <cstdint>

#define NV 4096
#define ALPHA 0.2f

// ---------------- device scratch ----------------
__device__ float g_Wh[NV * 64];
__device__ float g_e1[NV], g_e2[NV];
__device__ float g_E1[NV], g_E2[NV];
__device__ float g_A[NV], g_B[NV], g_thE[NV], g_dinv[NV];
__device__ float g_part[4][NV * 64];

// ---------------- K1: Wh = H@W + e1/e2 (4x4 register blocking, f32x2) --------
__global__ __launch_bounds__(256) void k1_wh(const float* __restrict__ H,
                                             const float* __restrict__ W,
                                             const float* __restrict__ a) {
    __shared__ float Hs[64][68];
    __shared__ float Ws[64][64];
    int tid = threadIdx.x;
    int tr = tid >> 4;   // row group of 4
    int tc = tid & 15;   // col group of 4
    int row0 = blockIdx.x * 64;

    unsigned long long acc[8];
#pragma unroll
    for (int q = 0; q < 8; q++) acc[q] = 0ull;

    for (int kk = 0; kk < 256; kk += 64) {
#pragma unroll
        for (int t = 0; t < 4; t++) {
            int u = tid + t * 256;
            int r = u >> 4, c4 = u & 15;
            *(float4*)&Hs[r][c4 * 4] = *(const float4*)&H[(size_t)(row0 + r) * 256 + kk + c4 * 4];
            *(float4*)&Ws[r][c4 * 4] = *(const float4*)&W[(size_t)(kk + r) * 64 + c4 * 4];
        }
        __syncthreads();
#pragma unroll 8
        for (int k = 0; k < 64; k++) {
            float4 w4 = *(const float4*)&Ws[k][tc * 4];
            unsigned long long w01, w23;
            asm("mov.b64 %0, {%1, %2};" : "=l"(w01) : "f"(w4.x), "f"(w4.y));
            asm("mov.b64 %0, {%1, %2};" : "=l"(w23) : "f"(w4.z), "f"(w4.w));
#pragma unroll
            for (int q = 0; q < 4; q++) {
                float h = Hs[tr * 4 + q][k];
                unsigned long long hp;
                asm("mov.b64 %0, {%1, %1};" : "=l"(hp) : "f"(h));
                asm("fma.rn.f32x2 %0, %1, %2, %0;" : "+l"(acc[q * 2 + 0]) : "l"(hp), "l"(w01));
                asm("fma.rn.f32x2 %0, %1, %2, %0;" : "+l"(acc[q * 2 + 1]) : "l"(hp), "l"(w23));
            }
        }
        __syncthreads();
    }

    float v[4][4];
#pragma unroll
    for (int q = 0; q < 4; q++) {
        v[q][0] = __uint_as_float((uint32_t)acc[q * 2 + 0]);
        v[q][1] = __uint_as_float((uint32_t)(acc[q * 2 + 0] >> 32));
        v[q][2] = __uint_as_float((uint32_t)acc[q * 2 + 1]);
        v[q][3] = __uint_as_float((uint32_t)(acc[q * 2 + 1] >> 32));
    }
    float a1c[4], a2c[4];
#pragma unroll
    for (int c = 0; c < 4; c++) {
        a1c[c] = __ldg(&a[tc * 4 + c]);
        a2c[c] = __ldg(&a[64 + tc * 4 + c]);
    }
#pragma unroll
    for (int q = 0; q < 4; q++) {
        int i = row0 + tr * 4 + q;
        *(float4*)&g_Wh[(size_t)i * 64 + tc * 4] = make_float4(v[q][0], v[q][1], v[q][2], v[q][3]);
        float p1 = v[q][0] * a1c[0] + v[q][1] * a1c[1] + v[q][2] * a1c[2] + v[q][3] * a1c[3];
        float p2 = v[q][0] * a2c[0] + v[q][1] * a2c[1] + v[q][2] * a2c[2] + v[q][3] * a2c[3];
#pragma unroll
        for (int off = 1; off < 16; off <<= 1) {
            p1 += __shfl_xor_sync(0xffffffffu, p1, off);
            p2 += __shfl_xor_sync(0xffffffffu, p2, off);
        }
        if (tc == 0) { g_e1[i] = p1; g_e2[i] = p2; }
    }
}

// ---------------- K1b: E1 = exp(e2), E2 = exp(alpha*e2) ----------------
__global__ __launch_bounds__(256) void k1b_exp() {
    int j = blockIdx.x * 256 + threadIdx.x;
    float v = g_e2[j];
    g_E1[j] = __expf(v);
    g_E2[j] = __expf(ALPHA * v);
}

// ---------------- K2: per-row m, A, B, thE, 1/denominator (smem-staged) ------
__global__ __launch_bounds__(256) void k2_denom() {
    __shared__ float sE1[NV];
    __shared__ float sE2[NV];
    __shared__ float red[8];
    int tid = threadIdx.x;
#pragma unroll
    for (int t = 0; t < 4; t++) {
        ((float4*)sE1)[tid + t * 256] = ((const float4*)g_E1)[tid + t * 256];
        ((float4*)sE2)[tid + t * 256] = ((const float4*)g_E2)[tid + t * 256];
    }
    float mx = -1e30f;
#pragma unroll
    for (int t = 0; t < 4; t++) {
        float4 v = ((const float4*)g_e2)[tid + t * 256];
        mx = fmaxf(fmaxf(mx, v.x), fmaxf(fmaxf(v.y, v.z), v.w));
    }
#pragma unroll
    for (int o = 16; o > 0; o >>= 1) mx = fmaxf(mx, __shfl_xor_sync(0xffffffffu, mx, o));
    if ((tid & 31) == 0) red[tid >> 5] = mx;
    __syncthreads();
    float e2max = red[0];
#pragma unroll
    for (int w = 1; w < 8; w++) e2max = fmaxf(e2max, red[w]);

    int il = tid >> 4;
    int sub = tid & 15;
    int i = blockIdx.x * 16 + il;
    float e1v = g_e1[i];
    float s = e1v + e2max;
    float m = s > 0.f ? s : ALPHA * s;
    float A = __expf(e1v - m);
    float B = __expf(ALPHA * e1v - m);
    float thE = __expf(-e1v);

    float d = 0.f;
#pragma unroll 4
    for (int t = 0; t < 64; t++) {
        int j = sub * 4 + t * 64;
        float4 E1v = *(const float4*)&sE1[j];
        float4 E2v = *(const float4*)&sE2[j];
        d += (E1v.x > thE) ? A * E1v.x : B * E2v.x;
        d += (E1v.y > thE) ? A * E1v.y : B * E2v.y;
        d += (E1v.z > thE) ? A * E1v.z : B * E2v.z;
        d += (E1v.w > thE) ? A * E1v.w : B * E2v.w;
    }
#pragma unroll
    for (int o = 8; o > 0; o >>= 1) d += __shfl_xor_sync(0xffffffffu, d, o);
    if (sub == 0) {
        g_A[i] = A; g_B[i] = B; g_thE[i] = thE;
        g_dinv[i] = 1.f / d;
    }
}

// ---------------- K3: masked weighted GEMM, 8i x 4c register tiles -----------
// Grid: 32 row-blocks (128 i) x 4 j-segments (1024 j) = 128 CTAs, 256 thr.
// Per 64-j chunk: cooperative build of ws[j][i] (i-contiguous -> natural f32x2
// pairs) + Whs[j][c]; then each thread does 16 FFMA2 per j.
// dyn smem: ws[64][128] @0 (32KB), Whs[64][64] @32KB (16KB),
//           sE1[1024] @48KB, sE2[1024] @52KB  -> 56KB total
#define K3_SMEM 57344
__global__ __launch_bounds__(256) void k3_main(const int* __restrict__ adj) {
    extern __shared__ float sm[];
    float* ws  = sm;            // [64][128]
    float* whs = sm + 8192;     // [64][64]
    float* sE1 = sm + 12288;    // [1024]
    float* sE2 = sm + 13312;    // [1024]

    int tid = threadIdx.x;
    int br = blockIdx.x >> 2;
    int jseg = blockIdx.x & 3;
    int jbase = jseg << 10;

    // stage E1/E2 for this j-segment
    ((float4*)sE1)[tid] = ((const float4*)(g_E1 + jbase))[tid];
    ((float4*)sE2)[tid] = ((const float4*)(g_E2 + jbase))[tid];

    // build role: row bi, j-half jh
    int bi = tid & 127;
    int jh = (tid >> 7) * 32;
    int gi = br * 128 + bi;
    float Ai = __ldg(&g_A[gi]), Bi = __ldg(&g_B[gi]), th = __ldg(&g_thE[gi]);
    const int4* adjp = (const int4*)(adj + (size_t)gi * NV + jbase + jh);

    // compute role: rows tr*8..+7, cols tc*4..+3
    int tr = tid >> 4;
    int tc = tid & 15;

    unsigned long long acc[16];   // [ip 0..3][c 0..3]
#pragma unroll
    for (int q = 0; q < 16; q++) acc[q] = 0ull;

    int4 pref[8];
#pragma unroll
    for (int q = 0; q < 8; q++) pref[q] = __ldg(adjp + q);

    for (int ch = 0; ch < 16; ++ch) {
        int4 cur[8];
#pragma unroll
        for (int q = 0; q < 8; q++) cur[q] = pref[q];
        if (ch < 15) {
#pragma unroll
            for (int q = 0; q < 8; q++) pref[q] = __ldg(adjp + (ch + 1) * 16 + q);
        }
        __syncthreads();   // previous chunk consumed (covers E1 staging on ch=0)

        // load Wh chunk: 64 rows x 64 cols
#pragma unroll
        for (int t = 0; t < 4; t++) {
            int u = tid + t * 256;
            int r = u >> 4, c4 = u & 15;
            *(float4*)&whs[r * 64 + c4 * 4] =
                *(const float4*)&g_Wh[(size_t)(jbase + ch * 64 + r) * 64 + c4 * 4];
        }
        // build masked-weight tile ws[j][i]
#pragma unroll
        for (int q = 0; q < 8; q++) {
            int4 av = cur[q];
            int jl = ch * 64 + jh + q * 4;
            float4 e1 = *(const float4*)&sE1[jl];
            float4 e2 = *(const float4*)&sE2[jl];
            float w0 = (av.x > 0) ? ((e1.x > th) ? Ai * e1.x : Bi * e2.x) : 0.f;
            float w1 = (av.y > 0) ? ((e1.y > th) ? Ai * e1.y : Bi * e2.y) : 0.f;
            float w2 = (av.z > 0) ? ((e1.z > th) ? Ai * e1.z : Bi * e2.z) : 0.f;
            float w3 = (av.w > 0) ? ((e1.w > th) ? Ai * e1.w : Bi * e2.w) : 0.f;
            int jr = (jh + q * 4) * 128 + bi;
            ws[jr]       = w0;
            ws[jr + 128] = w1;
            ws[jr + 256] = w2;
            ws[jr + 384] = w3;
        }
        __syncthreads();

        // compute: acc[ip][c] += {w_2ip, w_2ip+1} * {Wh_c, Wh_c}
#pragma unroll 4
        for (int jj = 0; jj < 64; jj++) {
            ulonglong2 wA = *(const ulonglong2*)&ws[jj * 128 + tr * 8];      // w0..w3
            ulonglong2 wB = *(const ulonglong2*)&ws[jj * 128 + tr * 8 + 4];  // w4..w7
            float4 wh = *(const float4*)&whs[jj * 64 + tc * 4];
            unsigned long long d0, d1, d2, d3;
            asm("mov.b64 %0, {%1, %1};" : "=l"(d0) : "f"(wh.x));
            asm("mov.b64 %0, {%1, %1};" : "=l"(d1) : "f"(wh.y));
            asm("mov.b64 %0, {%1, %1};" : "=l"(d2) : "f"(wh.z));
            asm("mov.b64 %0, {%1, %1};" : "=l"(d3) : "f"(wh.w));
            asm("fma.rn.f32x2 %0, %1, %2, %0;" : "+l"(acc[0])  : "l"(wA.x), "l"(d0));
            asm("fma.rn.f32x2 %0, %1, %2, %0;" : "+l"(acc[1])  : "l"(wA.x), "l"(d1));
            asm("fma.rn.f32x2 %0, %1, %2, %0;" : "+l"(acc[2])  : "l"(wA.x), "l"(d2));
            asm("fma.rn.f32x2 %0, %1, %2, %0;" : "+l"(acc[3])  : "l"(wA.x), "l"(d3));
            asm("fma.rn.f32x2 %0, %1, %2, %0;" : "+l"(acc[4])  : "l"(wA.y), "l"(d0));
            asm("fma.rn.f32x2 %0, %1, %2, %0;" : "+l"(acc[5])  : "l"(wA.y), "l"(d1));
            asm("fma.rn.f32x2 %0, %1, %2, %0;" : "+l"(acc[6])  : "l"(wA.y), "l"(d2));
            asm("fma.rn.f32x2 %0, %1, %2, %0;" : "+l"(acc[7])  : "l"(wA.y), "l"(d3));
            asm("fma.rn.f32x2 %0, %1, %2, %0;" : "+l"(acc[8])  : "l"(wB.x), "l"(d0));
            asm("fma.rn.f32x2 %0, %1, %2, %0;" : "+l"(acc[9])  : "l"(wB.x), "l"(d1));
            asm("fma.rn.f32x2 %0, %1, %2, %0;" : "+l"(acc[10]) : "l"(wB.x), "l"(d2));
            asm("fma.rn.f32x2 %0, %1, %2, %0;" : "+l"(acc[11]) : "l"(wB.x), "l"(d3));
            asm("fma.rn.f32x2 %0, %1, %2, %0;" : "+l"(acc[12]) : "l"(wB.y), "l"(d0));
            asm("fma.rn.f32x2 %0, %1, %2, %0;" : "+l"(acc[13]) : "l"(wB.y), "l"(d1));
            asm("fma.rn.f32x2 %0, %1, %2, %0;" : "+l"(acc[14]) : "l"(wB.y), "l"(d2));
            asm("fma.rn.f32x2 %0, %1, %2, %0;" : "+l"(acc[15]) : "l"(wB.y), "l"(d3));
        }
    }

    // write partials: acc[ip][c] lo -> row tr*8+2ip, hi -> row tr*8+2ip+1
    float* base = &g_part[jseg][(size_t)(br * 128 + tr * 8) * 64 + tc * 4];
#pragma unroll
    for (int ip = 0; ip < 4; ip++) {
        float4 lo, hi;
        lo.x = __uint_as_float((uint32_t)acc[ip * 4 + 0]);
        lo.y = __uint_as_float((uint32_t)acc[ip * 4 + 1]);
        lo.z = __uint_as_float((uint32_t)acc[ip * 4 + 2]);
        lo.w = __uint_as_float((uint32_t)acc[ip * 4 + 3]);
        hi.x = __uint_as_float((uint32_t)(acc[ip * 4 + 0] >> 32));
        hi.y = __uint_as_float((uint32_t)(acc[ip * 4 + 1] >> 32));
        hi.z = __uint_as_float((uint32_t)(acc[ip * 4 + 2] >> 32));
        hi.w = __uint_as_float((uint32_t)(acc[ip * 4 + 3] >> 32));
        *(float4*)(base + (ip * 2) * 64)     = lo;
        *(float4*)(base + (ip * 2 + 1) * 64) = hi;
    }
}

// ---------------- K4: combine partials, scale, ELU ----------------
__global__ __launch_bounds__(256) void k4_out(float* __restrict__ out) {
    int idx = blockIdx.x * 256 + threadIdx.x;
    float v = g_part[0][idx] + g_part[1][idx] + g_part[2][idx] + g_part[3][idx];
    int i = idx >> 6;
    v *= g_dinv[i];
    out[idx] = v > 0.f ? v : (__expf(v) - 1.f);
}

// ---------------- launch ----------------
extern "C" void kernel_launch(void* const* d_in, const int* in_sizes, int n_in,
                              void* d_out, int out_size) {
    const float* H = (const float*)d_in[0];
    const int* adj = (const int*)d_in[1];
    const float* W = (const float*)d_in[2];
    const float* a = (const float*)d_in[3];
    float* out = (float*)d_out;

    cudaFuncSetAttribute(k3_main, cudaFuncAttributeMaxDynamicSharedMemorySize, K3_SMEM);

    k1_wh<<<64, 256>>>(H, W, a);
    k1b_exp<<<16, 256>>>();
    k2_denom<<<256, 256>>>();
    k3_main<<<128, 256, K3_SMEM>>>(adj);
    k4_out<<<1024, 256>>>(out);
}